// round 16
// baseline (speedup 1.0000x reference)
#include <cuda_runtime.h>
#include <cstdint>

#define N_NODES 100000
#define N_EDGES 1600000
#define DIN 48
#define DOUT 128
#define OUT_ELEMS (N_NODES * DOUT)                     // 12,800,000
#define FULL_OUT  (OUT_ELEMS + 3 * N_EDGES + N_NODES)  // 17,700,000

#define SCAN_BLOCKS ((N_NODES + 1023) / 1024)          // 98

// Scratch node-feature buffers — written fully by gather, no zeroing.
__device__ float g_bufA[(size_t)N_NODES * DIN];
__device__ float g_bufB[(size_t)N_NODES * DIN];

// CSR-by-destination structures. g_off is zeroed by the PREVIOUS launch's
// mlp_kernel tail (zero-init at load covers the first call).
__device__ int    g_off[N_NODES + 1];
__device__ int    g_rank[N_EDGES];         // rank of edge within its dest node
__device__ int    g_bsum[SCAN_BLOCKS];
__device__ int    g_scan_ctr;              // zero-init; reset by last block
__device__ int    g_mlp_ctr;               // work-stealing counter (reset by scanAB)
__device__ float2 g_epay[N_EDGES];         // {src_as_float_bits, dfs}

// Fragment-major prepacked tf32 weights (hi only; 2xTF32 scheme).
#define W1F_FRAGS (2 * 8 * 6)               // 96  -> 3072 uint2
#define W2F_FRAGS (16 * 16)                 // 256 -> 8192 uint2
__device__ uint2 g_W1f[W1F_FRAGS * 32];
__device__ uint2 g_W2f[W2F_FRAGS * 32];

// ---------------------------------------------------------------------------
// tf32 helpers.
// ---------------------------------------------------------------------------
__device__ __forceinline__ void split_tf32(float x, uint32_t& hi, uint32_t& lo)
{
    float h, l;
    asm("cvt.rna.tf32.f32 %0, %1;" : "=f"(h) : "f"(x));
    float r = x - h;
    asm("cvt.rna.tf32.f32 %0, %1;" : "=f"(l) : "f"(r));
    hi = __float_as_uint(h);
    lo = __float_as_uint(l);
}

__device__ __forceinline__ uint32_t cvt_tf32(float x)
{
    float h;
    asm("cvt.rna.tf32.f32 %0, %1;" : "=f"(h) : "f"(x));
    return __float_as_uint(h);
}

__device__ __forceinline__ void mma_tf32(float d[4],
                                         uint32_t a0, uint32_t a1, uint32_t a2, uint32_t a3,
                                         uint32_t b0, uint32_t b1)
{
    asm volatile("mma.sync.aligned.m16n8k8.row.col.f32.tf32.tf32.f32 "
                 "{%0,%1,%2,%3}, {%4,%5,%6,%7}, {%8,%9}, {%0,%1,%2,%3};"
                 : "+f"(d[0]), "+f"(d[1]), "+f"(d[2]), "+f"(d[3])
                 : "r"(a0), "r"(a1), "r"(a2), "r"(a3), "r"(b0), "r"(b1));
}

// ---------------------------------------------------------------------------
// hist (x4 edges/thread, RETURN atomics -> per-edge rank) + fragment prepack.
// ---------------------------------------------------------------------------
#define HB  ((N_EDGES / 4 + 255) / 256)     // 1563
#define WB  64

__global__ void hist_and_split(const int* __restrict__ en,
                               const float* __restrict__ W1, const float* __restrict__ W2)
{
    if (blockIdx.x < HB) {
        int e0 = (blockIdx.x * blockDim.x + threadIdx.x) * 4;
        if (e0 + 4 <= N_EDGES) {
            int4 d4 = *(const int4*)(en + e0);
            int r0 = atomicAdd(&g_off[d4.x], 1);
            int r1 = atomicAdd(&g_off[d4.y], 1);
            int r2 = atomicAdd(&g_off[d4.z], 1);
            int r3 = atomicAdd(&g_off[d4.w], 1);
            *(int4*)(g_rank + e0) = make_int4(r0, r1, r2, r3);
        } else {
            for (int e = e0; e < N_EDGES; e++)
                g_rank[e] = atomicAdd(&g_off[__ldg(en + e)], 1);
        }
    } else {
        int i = (blockIdx.x - HB) * blockDim.x + threadIdx.x;
        if (i < W1F_FRAGS * 32) {
            int lane = i & 31;
            int frag = i >> 5;
            int ks   = frag % 6;
            int nt   = (frag / 6) & 7;
            int half = frag / 48;
            int r = lane >> 2, c = lane & 3;
            int ncol = half * 64 + nt * 8 + r;
            uint2 v;
            v.x = cvt_tf32(__ldg(W1 + (ks * 8 + c) * 128 + ncol));
            v.y = cvt_tf32(__ldg(W1 + (ks * 8 + c + 4) * 128 + ncol));
            g_W1f[i] = v;
        } else if (i < (W1F_FRAGS + W2F_FRAGS) * 32) {
            int j = i - W1F_FRAGS * 32;
            int lane = j & 31;
            int frag = j >> 5;
            int kk = frag & 15;
            int nt = frag >> 4;
            int r = lane >> 2, c = lane & 3;
            int ncol = nt * 8 + r;
            uint2 v;
            v.x = cvt_tf32(__ldg(W2 + (kk * 8 + c) * 128 + ncol));
            v.y = cvt_tf32(__ldg(W2 + (kk * 8 + c + 4) * 128 + ncol));
            g_W2f[j] = v;
        }
    }
}

// ---------------------------------------------------------------------------
// scanA+scanB fused (last-block-arrival pattern). Also resets g_mlp_ctr.
// ---------------------------------------------------------------------------
__global__ void scanAB()
{
    __shared__ int sh[256];
    __shared__ bool is_last;
    int tid = threadIdx.x;
    int base = blockIdx.x * 1024 + tid * 4;
    int s = 0;
    #pragma unroll
    for (int j = 0; j < 4; j++)
        s += (base + j < N_NODES) ? g_off[base + j] : 0;
    sh[tid] = s;
    __syncthreads();
    for (int d = 128; d > 0; d >>= 1) {
        if (tid < d) sh[tid] += sh[tid + d];
        __syncthreads();
    }
    if (tid == 0) {
        g_bsum[blockIdx.x] = sh[0];
        __threadfence();
        int c = atomicAdd(&g_scan_ctr, 1);
        is_last = (c == gridDim.x - 1);
    }
    __syncthreads();
    if (!is_last) return;

    int v = (tid < SCAN_BLOCKS) ? __ldcg(&g_bsum[tid]) : 0;
    __syncthreads();
    sh[tid] = v;
    __syncthreads();
    for (int d = 1; d < 256; d <<= 1) {
        int x = (tid >= d) ? sh[tid - d] : 0;
        __syncthreads();
        sh[tid] += x;
        __syncthreads();
    }
    if (tid < SCAN_BLOCKS) g_bsum[tid] = sh[tid] - v;
    if (tid == 0) { g_off[N_NODES] = sh[255]; g_scan_ctr = 0; g_mlp_ctr = 0; }
}

// ---------------------------------------------------------------------------
// Phase C: block-local exclusive scan + block prefix; offsets (counts -> off).
// TAIL: also echoes df into the output (coalesced DRAM STG, free here).
// ---------------------------------------------------------------------------
template <bool TAIL>
__global__ void scanC(const float* __restrict__ df, float* __restrict__ out)
{
    __shared__ int sh[256];
    int tid = threadIdx.x;
    int base = blockIdx.x * 1024 + tid * 4;
    int v[4];
    int s = 0;
    #pragma unroll
    for (int j = 0; j < 4; j++) {
        v[j] = (base + j < N_NODES) ? g_off[base + j] : 0;
        s += v[j];
    }
    sh[tid] = s;
    __syncthreads();
    for (int d = 1; d < 256; d <<= 1) {
        int x = (tid >= d) ? sh[tid - d] : 0;
        __syncthreads();
        sh[tid] += x;
        __syncthreads();
    }
    int ex = sh[tid] - s + g_bsum[blockIdx.x];
    #pragma unroll
    for (int j = 0; j < 4; j++) {
        if (base + j < N_NODES) {
            g_off[base + j] = ex;
            if (TAIL)
                out[OUT_ELEMS + 3 * N_EDGES + base + j] = __ldg(df + base + j);
        }
        ex += v[j];
    }
}

// ---------------------------------------------------------------------------
// fill: ATOMIC-FREE. pos = off[en[e]] + rank[e]. Pure loads + one STG.
// TAIL: echoes sn/en/dfs as coalesced scalar stores.
// ---------------------------------------------------------------------------
#define EB ((N_EDGES + 255) / 256)          // 6250

template <bool TAIL>
__global__ void fill_kernel(const int* __restrict__ sn, const int* __restrict__ en,
                            const float* __restrict__ dfs, float* __restrict__ out)
{
    int e = blockIdx.x * blockDim.x + threadIdx.x;
    if (e >= N_EDGES) return;
    int s = __ldg(sn + e);
    int d = __ldg(en + e);
    float f = __ldg(dfs + e);
    int pos = __ldg(&g_off[d]) + __ldg(&g_rank[e]);
    g_epay[pos] = make_float2(__int_as_float(s), f);
    if (TAIL) {
        float* p = out + OUT_ELEMS;
        p[e]               = (float)s;
        p[N_EDGES + e]     = (float)d;
        p[2 * N_EDGES + e] = f;
    }
}

// ---------------------------------------------------------------------------
// Gather pass: dst[n] = df[n] * sum_{e: end=n} src[start_e] * dfs_e
// 12 threads per node, one float4 chunk each, unrolled x4.
// ---------------------------------------------------------------------------
#define GB ((N_NODES * 12 + 255) / 256)     // 4688

__global__ void gather_pass(const float* __restrict__ src, float* __restrict__ dst,
                            const float* __restrict__ df)
{
    int t = blockIdx.x * blockDim.x + threadIdx.x;
    if (t >= N_NODES * 12) return;
    int n = t / 12;
    int q = t - n * 12;

    int o0 = __ldg(&g_off[n]);
    int o1 = __ldg(&g_off[n + 1]);

    float4 acc = make_float4(0.f, 0.f, 0.f, 0.f);
    int i = o0;
    for (; i + 4 <= o1; i += 4) {
        float2 p0 = __ldg(&g_epay[i]);
        float2 p1 = __ldg(&g_epay[i + 1]);
        float2 p2 = __ldg(&g_epay[i + 2]);
        float2 p3 = __ldg(&g_epay[i + 3]);
        float4 v0 = __ldg((const float4*)(src + (size_t)__float_as_int(p0.x) * DIN) + q);
        float4 v1 = __ldg((const float4*)(src + (size_t)__float_as_int(p1.x) * DIN) + q);
        float4 v2 = __ldg((const float4*)(src + (size_t)__float_as_int(p2.x) * DIN) + q);
        float4 v3 = __ldg((const float4*)(src + (size_t)__float_as_int(p3.x) * DIN) + q);
        acc.x = fmaf(v0.x, p0.y, acc.x); acc.y = fmaf(v0.y, p0.y, acc.y);
        acc.z = fmaf(v0.z, p0.y, acc.z); acc.w = fmaf(v0.w, p0.y, acc.w);
        acc.x = fmaf(v1.x, p1.y, acc.x); acc.y = fmaf(v1.y, p1.y, acc.y);
        acc.z = fmaf(v1.z, p1.y, acc.z); acc.w = fmaf(v1.w, p1.y, acc.w);
        acc.x = fmaf(v2.x, p2.y, acc.x); acc.y = fmaf(v2.y, p2.y, acc.y);
        acc.z = fmaf(v2.z, p2.y, acc.z); acc.w = fmaf(v2.w, p2.y, acc.w);
        acc.x = fmaf(v3.x, p3.y, acc.x); acc.y = fmaf(v3.y, p3.y, acc.y);
        acc.z = fmaf(v3.z, p3.y, acc.z); acc.w = fmaf(v3.w, p3.y, acc.w);
    }
    for (; i < o1; i++) {
        float2 p = __ldg(&g_epay[i]);
        float4 v = __ldg((const float4*)(src + (size_t)__float_as_int(p.x) * DIN) + q);
        acc.x = fmaf(v.x, p.y, acc.x); acc.y = fmaf(v.y, p.y, acc.y);
        acc.z = fmaf(v.z, p.y, acc.z); acc.w = fmaf(v.w, p.y, acc.w);
    }

    float f = __ldg(df + n);
    acc.x *= f; acc.y *= f; acc.z *= f; acc.w *= f;
    ((float4*)(dst + (size_t)n * DIN))[q] = acc;
}

// ---------------------------------------------------------------------------
// Persistent fused MLP on tensor cores (2xTF32: hi*hi + lo*hi):
//   out = relu(x @ W1 + b1) @ W2 + b2
// Fragment-major smem weights (LDS.64, zero index ALU). A loads hoisted out
// of the half loop (x read once per group). Tail threads re-zero g_off for
// the next replay (replaces the serialized memset node).
// ---------------------------------------------------------------------------
#define MLP_THREADS 384
#define MLP_GRID 148
#define N_GROUPS ((N_NODES + 15) / 16)                 // 6250
#define MLP_SMEM_WORDS ((W1F_FRAGS + W2F_FRAGS) * 32 * 2 + 256)

__global__ void __launch_bounds__(MLP_THREADS, 1)
mlp_kernel(const float* __restrict__ x,
           const float* __restrict__ b1, const float* __restrict__ b2,
           float* __restrict__ out)
{
    extern __shared__ uint32_t smu[];
    uint2* W1fs = (uint2*)smu;                       // [96][32]
    uint2* W2fs = W1fs + W1F_FRAGS * 32;             // [256][32]
    float* b1s  = (float*)(W2fs + W2F_FRAGS * 32);   // [128]
    float* b2s  = b1s + 128;

    int tid = threadIdx.x;

    for (int i = tid; i < W1F_FRAGS * 32; i += MLP_THREADS) W1fs[i] = g_W1f[i];
    for (int i = tid; i < W2F_FRAGS * 32; i += MLP_THREADS) W2fs[i] = g_W2f[i];
    if (tid < 128) { b1s[tid] = __ldg(b1 + tid); b2s[tid] = __ldg(b2 + tid); }
    __syncthreads();

    int lane = tid & 31;
    int r = lane >> 2;
    int c = lane & 3;
    int srcA = (lane & ~3) | (c >> 1);
    int srcB = srcA + 2;
    bool odd = (c & 1);

    const uint2* w1p = W1fs + lane;
    const uint2* w2p = W2fs + lane;

    while (true) {
        int g = 0;
        if (lane == 0) g = atomicAdd(&g_mlp_ctr, 1);
        g = __shfl_sync(0xFFFFFFFFu, g, 0);
        if (g >= N_GROUPS) break;

        int node0 = g * 16;
        int row0 = node0 + r;
        int row1 = row0 + 8;
        bool ok0 = row0 < N_NODES;
        bool ok1 = row1 < N_NODES;
        const float* y0 = x + (size_t)row0 * DIN;
        const float* y1 = x + (size_t)row1 * DIN;

        // A-operand loads hoisted: x rows read ONCE per group.
        float af[6][4];
        #pragma unroll
        for (int ks = 0; ks < 6; ks++) {
            int k0 = ks * 8;
            af[ks][0] = ok0 ? __ldg(y0 + k0 + c)     : 0.f;
            af[ks][1] = ok1 ? __ldg(y1 + k0 + c)     : 0.f;
            af[ks][2] = ok0 ? __ldg(y0 + k0 + c + 4) : 0.f;
            af[ks][3] = ok1 ? __ldg(y1 + k0 + c + 4) : 0.f;
        }

        float d2[16][4];
        #pragma unroll
        for (int nt = 0; nt < 16; nt++) {
            d2[nt][0] = b2s[nt * 8 + 2 * c];
            d2[nt][1] = b2s[nt * 8 + 2 * c + 1];
            d2[nt][2] = d2[nt][0];
            d2[nt][3] = d2[nt][1];
        }

        #pragma unroll
        for (int half = 0; half < 2; half++) {
            // ---- stage 1 (half): H[:, half*64 .. half*64+63] ----
            float h[8][4];
            #pragma unroll
            for (int nt = 0; nt < 8; nt++) {
                int n0 = half * 64 + nt * 8;
                h[nt][0] = b1s[n0 + 2 * c];
                h[nt][1] = b1s[n0 + 2 * c + 1];
                h[nt][2] = h[nt][0];
                h[nt][3] = h[nt][1];
            }
            #pragma unroll
            for (int ks = 0; ks < 6; ks++) {
                uint32_t ah[4], al[4];
                split_tf32(af[ks][0], ah[0], al[0]);
                split_tf32(af[ks][1], ah[1], al[1]);
                split_tf32(af[ks][2], ah[2], al[2]);
                split_tf32(af[ks][3], ah[3], al[3]);
                #pragma unroll
                for (int nt = 0; nt < 8; nt++) {
                    uint2 b = w1p[((half * 8 + nt) * 6 + ks) * 32];
                    mma_tf32(h[nt], ah[0], ah[1], ah[2], ah[3], b.x, b.y);   // hi*hi
                    mma_tf32(h[nt], al[0], al[1], al[2], al[3], b.x, b.y);   // lo*hi
                }
            }
            #pragma unroll
            for (int nt = 0; nt < 8; nt++) {
                h[nt][0] = fmaxf(h[nt][0], 0.f);
                h[nt][1] = fmaxf(h[nt][1], 0.f);
                h[nt][2] = fmaxf(h[nt][2], 0.f);
                h[nt][3] = fmaxf(h[nt][3], 0.f);
            }

            // ---- stage 2 partial: d2 += H[:, kk*8..kk*8+7] @ W2[...] ----
            #pragma unroll
            for (int ks2 = 0; ks2 < 8; ks2++) {
                int kk = half * 8 + ks2;
                float w0 = __shfl_sync(0xFFFFFFFFu, h[ks2][0], srcA);
                float w1 = __shfl_sync(0xFFFFFFFFu, h[ks2][1], srcA);
                float w2 = __shfl_sync(0xFFFFFFFFu, h[ks2][2], srcA);
                float w3 = __shfl_sync(0xFFFFFFFFu, h[ks2][3], srcA);
                float x0 = __shfl_sync(0xFFFFFFFFu, h[ks2][0], srcB);
                float x1 = __shfl_sync(0xFFFFFFFFu, h[ks2][1], srcB);
                float x2 = __shfl_sync(0xFFFFFFFFu, h[ks2][2], srcB);
                float x3 = __shfl_sync(0xFFFFFFFFu, h[ks2][3], srcB);
                uint32_t ah[4], al[4];
                split_tf32(odd ? w1 : w0, ah[0], al[0]);
                split_tf32(odd ? w3 : w2, ah[1], al[1]);
                split_tf32(odd ? x1 : x0, ah[2], al[2]);
                split_tf32(odd ? x3 : x2, ah[3], al[3]);
                #pragma unroll
                for (int nt = 0; nt < 16; nt++) {
                    uint2 b = w2p[(nt * 16 + kk) * 32];
                    mma_tf32(d2[nt], ah[0], ah[1], ah[2], ah[3], b.x, b.y);
                    mma_tf32(d2[nt], al[0], al[1], al[2], al[3], b.x, b.y);
                }
            }
        }

        // ---- store ----
        #pragma unroll
        for (int nt = 0; nt < 16; nt++) {
            if (ok0)
                *(float2*)(out + (size_t)row0 * 128 + nt * 8 + 2 * c) =
                    make_float2(d2[nt][0], d2[nt][1]);
            if (ok1)
                *(float2*)(out + (size_t)row1 * 128 + nt * 8 + 2 * c) =
                    make_float2(d2[nt][2], d2[nt][3]);
        }
    }

    // ---- tail: re-zero the histogram for the next replay (replaces memset) ----
    for (int i = blockIdx.x * MLP_THREADS + tid; i < N_NODES; i += MLP_GRID * MLP_THREADS)
        g_off[i] = 0;
}

extern "C" void kernel_launch(void* const* d_in, const int* in_sizes, int n_in,
                              void* d_out, int out_size)
{
    const float* y   = (const float*)d_in[0];
    const int*   sn  = (const int*)  d_in[1];
    const int*   en  = (const int*)  d_in[2];
    const float* dfs = (const float*)d_in[3];
    const float* df  = (const float*)d_in[4];
    const float* W1  = (const float*)d_in[5];
    const float* b1  = (const float*)d_in[6];
    const float* W2  = (const float*)d_in[7];
    const float* b2  = (const float*)d_in[8];
    float* out = (float*)d_out;

    float *bufA, *bufB;
    cudaGetSymbolAddress((void**)&bufA, g_bufA);
    cudaGetSymbolAddress((void**)&bufB, g_bufB);

    cudaFuncSetAttribute(mlp_kernel, cudaFuncAttributeMaxDynamicSharedMemorySize,
                         MLP_SMEM_WORDS * (int)sizeof(uint32_t));

    const bool tail = (out_size >= FULL_OUT);

    // ---- CSR build (g_off pre-zeroed by previous launch / static init) ----
    hist_and_split<<<HB + WB, 256>>>(en, W1, W2);
    scanAB<<<SCAN_BLOCKS, 256>>>();
    if (tail) {
        scanC<true><<<SCAN_BLOCKS, 256>>>(df, out);
        fill_kernel<true><<<EB, 256>>>(sn, en, dfs, out);
    } else {
        scanC<false><<<SCAN_BLOCKS, 256>>>(df, out);
        fill_kernel<false><<<EB, 256>>>(sn, en, dfs, out);
    }

    // ---- two gather passes ----
    gather_pass<<<GB, 256>>>(y,    bufA, df);
    gather_pass<<<GB, 256>>>(bufA, bufB, df);

    // ---- persistent fused tensor-core MLP (2xTF32), zeroes g_off at tail ----
    mlp_kernel<<<MLP_GRID, MLP_THREADS,
                 MLP_SMEM_WORDS * sizeof(uint32_t)>>>(bufB, b1, b2, out);
}

// round 17
// speedup vs baseline: 1.0125x; 1.0125x over previous
#include <cuda_runtime.h>
#include <cstdint>

#define N_NODES 100000
#define N_EDGES 1600000
#define DIN 48
#define DOUT 128
#define OUT_ELEMS (N_NODES * DOUT)                     // 12,800,000
#define FULL_OUT  (OUT_ELEMS + 3 * N_EDGES + N_NODES)  // 17,700,000

#define SCAN_BLOCKS ((N_NODES + 1023) / 1024)          // 98

// Scratch node-feature buffers — written fully by gather, no zeroing.
__device__ float g_bufA[(size_t)N_NODES * DIN];
__device__ float g_bufB[(size_t)N_NODES * DIN];

// CSR-by-destination structures. g_off and g_scan_ctr are reset by the
// PREVIOUS launch's mlp_kernel tail (zero-init at load covers call #1).
__device__ int    g_off[N_NODES + 1];
__device__ int    g_rank[N_EDGES];         // rank of edge within its dest node
__device__ int    g_bsum[SCAN_BLOCKS];
__device__ int    g_scan_ctr;              // publication counter
__device__ int    g_mlp_ctr;               // work-stealing counter (reset by scan)
__device__ float2 g_epay[N_EDGES];         // {src_as_float_bits, dfs}

// Fragment-major prepacked tf32 weights (hi only; 2xTF32 scheme).
#define W1F_FRAGS (2 * 8 * 6)               // 96  -> 3072 uint2
#define W2F_FRAGS (16 * 16)                 // 256 -> 8192 uint2
__device__ uint2 g_W1f[W1F_FRAGS * 32];
__device__ uint2 g_W2f[W2F_FRAGS * 32];

// ---------------------------------------------------------------------------
// tf32 helpers.
// ---------------------------------------------------------------------------
__device__ __forceinline__ void split_tf32(float x, uint32_t& hi, uint32_t& lo)
{
    float h, l;
    asm("cvt.rna.tf32.f32 %0, %1;" : "=f"(h) : "f"(x));
    float r = x - h;
    asm("cvt.rna.tf32.f32 %0, %1;" : "=f"(l) : "f"(r));
    hi = __float_as_uint(h);
    lo = __float_as_uint(l);
}

__device__ __forceinline__ uint32_t cvt_tf32(float x)
{
    float h;
    asm("cvt.rna.tf32.f32 %0, %1;" : "=f"(h) : "f"(x));
    return __float_as_uint(h);
}

__device__ __forceinline__ void mma_tf32(float d[4],
                                         uint32_t a0, uint32_t a1, uint32_t a2, uint32_t a3,
                                         uint32_t b0, uint32_t b1)
{
    asm volatile("mma.sync.aligned.m16n8k8.row.col.f32.tf32.tf32.f32 "
                 "{%0,%1,%2,%3}, {%4,%5,%6,%7}, {%8,%9}, {%0,%1,%2,%3};"
                 : "+f"(d[0]), "+f"(d[1]), "+f"(d[2]), "+f"(d[3])
                 : "r"(a0), "r"(a1), "r"(a2), "r"(a3), "r"(b0), "r"(b1));
}

// ---------------------------------------------------------------------------
// hist (x4 edges/thread, RETURN atomics -> per-edge rank) + fragment prepack.
// ---------------------------------------------------------------------------
#define HB  ((N_EDGES / 4 + 255) / 256)     // 1563
#define WB  64

__global__ void hist_and_split(const int* __restrict__ en,
                               const float* __restrict__ W1, const float* __restrict__ W2)
{
    if (blockIdx.x < HB) {
        int e0 = (blockIdx.x * blockDim.x + threadIdx.x) * 4;
        if (e0 + 4 <= N_EDGES) {
            int4 d4 = *(const int4*)(en + e0);
            int r0 = atomicAdd(&g_off[d4.x], 1);
            int r1 = atomicAdd(&g_off[d4.y], 1);
            int r2 = atomicAdd(&g_off[d4.z], 1);
            int r3 = atomicAdd(&g_off[d4.w], 1);
            *(int4*)(g_rank + e0) = make_int4(r0, r1, r2, r3);
        } else {
            for (int e = e0; e < N_EDGES; e++)
                g_rank[e] = atomicAdd(&g_off[__ldg(en + e)], 1);
        }
    } else {
        int i = (blockIdx.x - HB) * blockDim.x + threadIdx.x;
        if (i < W1F_FRAGS * 32) {
            int lane = i & 31;
            int frag = i >> 5;
            int ks   = frag % 6;
            int nt   = (frag / 6) & 7;
            int half = frag / 48;
            int r = lane >> 2, c = lane & 3;
            int ncol = half * 64 + nt * 8 + r;
            uint2 v;
            v.x = cvt_tf32(__ldg(W1 + (ks * 8 + c) * 128 + ncol));
            v.y = cvt_tf32(__ldg(W1 + (ks * 8 + c + 4) * 128 + ncol));
            g_W1f[i] = v;
        } else if (i < (W1F_FRAGS + W2F_FRAGS) * 32) {
            int j = i - W1F_FRAGS * 32;
            int lane = j & 31;
            int frag = j >> 5;
            int kk = frag & 15;
            int nt = frag >> 4;
            int r = lane >> 2, c = lane & 3;
            int ncol = nt * 8 + r;
            uint2 v;
            v.x = cvt_tf32(__ldg(W2 + (kk * 8 + c) * 128 + ncol));
            v.y = cvt_tf32(__ldg(W2 + (kk * 8 + c + 4) * 128 + ncol));
            g_W2f[j] = v;
        }
    }
}

// ---------------------------------------------------------------------------
// Single-kernel scan: per-block sums -> publish -> ALL blocks spin until all
// 98 sums are published -> each block computes its own prefix and writes
// offsets from register-held counts. 98 blocks <= 148 SMs (co-resident, no
// deadlock). Block 97 writes the sentinel + resets g_mlp_ctr.
// TAIL: also echoes df into the output.
// ---------------------------------------------------------------------------
template <bool TAIL>
__global__ void scan_fused(const float* __restrict__ df, float* __restrict__ out)
{
    __shared__ int sh[256];
    int tid = threadIdx.x;
    int b   = blockIdx.x;
    int base = b * 1024 + tid * 4;

    // phase 1: local counts + block sum
    int v[4];
    int s = 0;
    #pragma unroll
    for (int j = 0; j < 4; j++) {
        v[j] = (base + j < N_NODES) ? g_off[base + j] : 0;
        s += v[j];
    }
    sh[tid] = s;
    __syncthreads();
    for (int d = 128; d > 0; d >>= 1) {
        if (tid < d) sh[tid] += sh[tid + d];
        __syncthreads();
    }
    if (tid == 0) {
        g_bsum[b] = sh[0];
        __threadfence();
        atomicAdd(&g_scan_ctr, 1);
        // spin until all blocks have published
        while (atomicAdd(&g_scan_ctr, 0) < SCAN_BLOCKS) { __nanosleep(64); }
    }
    __syncthreads();

    // phase 2: block prefix = sum of predecessors' published sums
    int contrib = (tid < b) ? __ldcg(&g_bsum[tid]) : 0;
    int all     = (tid < SCAN_BLOCKS) ? ((tid < b) ? contrib : __ldcg(&g_bsum[tid])) : 0;
    sh[tid] = contrib;
    __syncthreads();
    for (int d = 128; d > 0; d >>= 1) {
        if (tid < d) sh[tid] += sh[tid + d];
        __syncthreads();
    }
    int prefix = sh[0];
    __syncthreads();

    if (b == SCAN_BLOCKS - 1) {
        // total = prefix + own sum; also reset the MLP work counter
        sh[tid] = all;
        __syncthreads();
        for (int d = 128; d > 0; d >>= 1) {
            if (tid < d) sh[tid] += sh[tid + d];
            __syncthreads();
        }
        if (tid == 0) { g_off[N_NODES] = sh[0]; g_mlp_ctr = 0; }
        __syncthreads();
    }

    // phase 3: block-local exclusive scan of thread sums; write offsets
    sh[tid] = s;
    __syncthreads();
    for (int d = 1; d < 256; d <<= 1) {
        int x = (tid >= d) ? sh[tid - d] : 0;
        __syncthreads();
        sh[tid] += x;
        __syncthreads();
    }
    int ex = sh[tid] - s + prefix;
    #pragma unroll
    for (int j = 0; j < 4; j++) {
        if (base + j < N_NODES) {
            g_off[base + j] = ex;
            if (TAIL)
                out[OUT_ELEMS + 3 * N_EDGES + base + j] = __ldg(df + base + j);
        }
        ex += v[j];
    }
}

// ---------------------------------------------------------------------------
// fill: ATOMIC-FREE. pos = off[en[e]] + rank[e]. Pure loads + one STG.
// TAIL: echoes sn/en/dfs as coalesced scalar stores.
// ---------------------------------------------------------------------------
#define EB ((N_EDGES + 255) / 256)          // 6250

template <bool TAIL>
__global__ void fill_kernel(const int* __restrict__ sn, const int* __restrict__ en,
                            const float* __restrict__ dfs, float* __restrict__ out)
{
    int e = blockIdx.x * blockDim.x + threadIdx.x;
    if (e >= N_EDGES) return;
    int s = __ldg(sn + e);
    int d = __ldg(en + e);
    float f = __ldg(dfs + e);
    int pos = __ldg(&g_off[d]) + __ldg(&g_rank[e]);
    g_epay[pos] = make_float2(__int_as_float(s), f);
    if (TAIL) {
        float* p = out + OUT_ELEMS;
        p[e]               = (float)s;
        p[N_EDGES + e]     = (float)d;
        p[2 * N_EDGES + e] = f;
    }
}

// ---------------------------------------------------------------------------
// Gather pass: dst[n] = df[n] * sum_{e: end=n} src[start_e] * dfs_e
// 12 threads per node, one float4 chunk each, unrolled x4.
// ---------------------------------------------------------------------------
#define GB ((N_NODES * 12 + 255) / 256)     // 4688

__global__ void gather_pass(const float* __restrict__ src, float* __restrict__ dst,
                            const float* __restrict__ df)
{
    int t = blockIdx.x * blockDim.x + threadIdx.x;
    if (t >= N_NODES * 12) return;
    int n = t / 12;
    int q = t - n * 12;

    int o0 = __ldg(&g_off[n]);
    int o1 = __ldg(&g_off[n + 1]);

    float4 acc = make_float4(0.f, 0.f, 0.f, 0.f);
    int i = o0;
    for (; i + 4 <= o1; i += 4) {
        float2 p0 = __ldg(&g_epay[i]);
        float2 p1 = __ldg(&g_epay[i + 1]);
        float2 p2 = __ldg(&g_epay[i + 2]);
        float2 p3 = __ldg(&g_epay[i + 3]);
        float4 v0 = __ldg((const float4*)(src + (size_t)__float_as_int(p0.x) * DIN) + q);
        float4 v1 = __ldg((const float4*)(src + (size_t)__float_as_int(p1.x) * DIN) + q);
        float4 v2 = __ldg((const float4*)(src + (size_t)__float_as_int(p2.x) * DIN) + q);
        float4 v3 = __ldg((const float4*)(src + (size_t)__float_as_int(p3.x) * DIN) + q);
        acc.x = fmaf(v0.x, p0.y, acc.x); acc.y = fmaf(v0.y, p0.y, acc.y);
        acc.z = fmaf(v0.z, p0.y, acc.z); acc.w = fmaf(v0.w, p0.y, acc.w);
        acc.x = fmaf(v1.x, p1.y, acc.x); acc.y = fmaf(v1.y, p1.y, acc.y);
        acc.z = fmaf(v1.z, p1.y, acc.z); acc.w = fmaf(v1.w, p1.y, acc.w);
        acc.x = fmaf(v2.x, p2.y, acc.x); acc.y = fmaf(v2.y, p2.y, acc.y);
        acc.z = fmaf(v2.z, p2.y, acc.z); acc.w = fmaf(v2.w, p2.y, acc.w);
        acc.x = fmaf(v3.x, p3.y, acc.x); acc.y = fmaf(v3.y, p3.y, acc.y);
        acc.z = fmaf(v3.z, p3.y, acc.z); acc.w = fmaf(v3.w, p3.y, acc.w);
    }
    for (; i < o1; i++) {
        float2 p = __ldg(&g_epay[i]);
        float4 v = __ldg((const float4*)(src + (size_t)__float_as_int(p.x) * DIN) + q);
        acc.x = fmaf(v.x, p.y, acc.x); acc.y = fmaf(v.y, p.y, acc.y);
        acc.z = fmaf(v.z, p.y, acc.z); acc.w = fmaf(v.w, p.y, acc.w);
    }

    float f = __ldg(df + n);
    acc.x *= f; acc.y *= f; acc.z *= f; acc.w *= f;
    ((float4*)(dst + (size_t)n * DIN))[q] = acc;
}

// ---------------------------------------------------------------------------
// Persistent fused MLP on tensor cores (2xTF32: hi*hi + lo*hi):
//   out = relu(x @ W1 + b1) @ W2 + b2
// Fragment-major smem weights (LDS.64, zero index ALU). R15's exact hot loop.
// Tail threads re-zero g_off and g_scan_ctr for the next replay.
// ---------------------------------------------------------------------------
#define MLP_THREADS 384
#define MLP_GRID 148
#define N_GROUPS ((N_NODES + 15) / 16)                 // 6250
#define MLP_SMEM_WORDS ((W1F_FRAGS + W2F_FRAGS) * 32 * 2 + 256)

__global__ void __launch_bounds__(MLP_THREADS, 1)
mlp_kernel(const float* __restrict__ x,
           const float* __restrict__ b1, const float* __restrict__ b2,
           float* __restrict__ out)
{
    extern __shared__ uint32_t smu[];
    uint2* W1fs = (uint2*)smu;                       // [96][32]
    uint2* W2fs = W1fs + W1F_FRAGS * 32;             // [256][32]
    float* b1s  = (float*)(W2fs + W2F_FRAGS * 32);   // [128]
    float* b2s  = b1s + 128;

    int tid = threadIdx.x;

    for (int i = tid; i < W1F_FRAGS * 32; i += MLP_THREADS) W1fs[i] = g_W1f[i];
    for (int i = tid; i < W2F_FRAGS * 32; i += MLP_THREADS) W2fs[i] = g_W2f[i];
    if (tid < 128) { b1s[tid] = __ldg(b1 + tid); b2s[tid] = __ldg(b2 + tid); }
    __syncthreads();

    int lane = tid & 31;
    int r = lane >> 2;
    int c = lane & 3;
    int srcA = (lane & ~3) | (c >> 1);
    int srcB = srcA + 2;
    bool odd = (c & 1);

    const uint2* w1p = W1fs + lane;
    const uint2* w2p = W2fs + lane;

    while (true) {
        int g = 0;
        if (lane == 0) g = atomicAdd(&g_mlp_ctr, 1);
        g = __shfl_sync(0xFFFFFFFFu, g, 0);
        if (g >= N_GROUPS) break;

        int node0 = g * 16;
        int row0 = node0 + r;
        int row1 = row0 + 8;
        bool ok0 = row0 < N_NODES;
        bool ok1 = row1 < N_NODES;
        const float* y0 = x + (size_t)row0 * DIN;
        const float* y1 = x + (size_t)row1 * DIN;

        float d2[16][4];
        #pragma unroll
        for (int nt = 0; nt < 16; nt++) {
            d2[nt][0] = b2s[nt * 8 + 2 * c];
            d2[nt][1] = b2s[nt * 8 + 2 * c + 1];
            d2[nt][2] = d2[nt][0];
            d2[nt][3] = d2[nt][1];
        }

        #pragma unroll
        for (int half = 0; half < 2; half++) {
            // ---- stage 1 (half): H[:, half*64 .. half*64+63] ----
            float h[8][4];
            #pragma unroll
            for (int nt = 0; nt < 8; nt++) {
                int n0 = half * 64 + nt * 8;
                h[nt][0] = b1s[n0 + 2 * c];
                h[nt][1] = b1s[n0 + 2 * c + 1];
                h[nt][2] = h[nt][0];
                h[nt][3] = h[nt][1];
            }
            #pragma unroll
            for (int ks = 0; ks < 6; ks++) {
                int k0 = ks * 8;
                float a0 = ok0 ? __ldg(y0 + k0 + c)     : 0.f;
                float a1 = ok1 ? __ldg(y1 + k0 + c)     : 0.f;
                float a2 = ok0 ? __ldg(y0 + k0 + c + 4) : 0.f;
                float a3 = ok1 ? __ldg(y1 + k0 + c + 4) : 0.f;
                uint32_t ah[4], al[4];
                split_tf32(a0, ah[0], al[0]);
                split_tf32(a1, ah[1], al[1]);
                split_tf32(a2, ah[2], al[2]);
                split_tf32(a3, ah[3], al[3]);
                #pragma unroll
                for (int nt = 0; nt < 8; nt++) {
                    uint2 b = w1p[((half * 8 + nt) * 6 + ks) * 32];
                    mma_tf32(h[nt], ah[0], ah[1], ah[2], ah[3], b.x, b.y);   // hi*hi
                    mma_tf32(h[nt], al[0], al[1], al[2], al[3], b.x, b.y);   // lo*hi
                }
            }
            #pragma unroll
            for (int nt = 0; nt < 8; nt++) {
                h[nt][0] = fmaxf(h[nt][0], 0.f);
                h[nt][1] = fmaxf(h[nt][1], 0.f);
                h[nt][2] = fmaxf(h[nt][2], 0.f);
                h[nt][3] = fmaxf(h[nt][3], 0.f);
            }

            // ---- stage 2 partial: d2 += H[:, kk*8..kk*8+7] @ W2[...] ----
            #pragma unroll
            for (int ks2 = 0; ks2 < 8; ks2++) {
                int kk = half * 8 + ks2;
                float w0 = __shfl_sync(0xFFFFFFFFu, h[ks2][0], srcA);
                float w1 = __shfl_sync(0xFFFFFFFFu, h[ks2][1], srcA);
                float w2 = __shfl_sync(0xFFFFFFFFu, h[ks2][2], srcA);
                float w3 = __shfl_sync(0xFFFFFFFFu, h[ks2][3], srcA);
                float x0 = __shfl_sync(0xFFFFFFFFu, h[ks2][0], srcB);
                float x1 = __shfl_sync(0xFFFFFFFFu, h[ks2][1], srcB);
                float x2 = __shfl_sync(0xFFFFFFFFu, h[ks2][2], srcB);
                float x3 = __shfl_sync(0xFFFFFFFFu, h[ks2][3], srcB);
                uint32_t ah[4], al[4];
                split_tf32(odd ? w1 : w0, ah[0], al[0]);
                split_tf32(odd ? w3 : w2, ah[1], al[1]);
                split_tf32(odd ? x1 : x0, ah[2], al[2]);
                split_tf32(odd ? x3 : x2, ah[3], al[3]);
                #pragma unroll
                for (int nt = 0; nt < 16; nt++) {
                    uint2 b = w2p[(nt * 16 + kk) * 32];
                    mma_tf32(d2[nt], ah[0], ah[1], ah[2], ah[3], b.x, b.y);
                    mma_tf32(d2[nt], al[0], al[1], al[2], al[3], b.x, b.y);
                }
            }
        }

        // ---- store ----
        #pragma unroll
        for (int nt = 0; nt < 16; nt++) {
            if (ok0)
                *(float2*)(out + (size_t)row0 * 128 + nt * 8 + 2 * c) =
                    make_float2(d2[nt][0], d2[nt][1]);
            if (ok1)
                *(float2*)(out + (size_t)row1 * 128 + nt * 8 + 2 * c) =
                    make_float2(d2[nt][2], d2[nt][3]);
        }
    }

    // ---- tail: reset histogram + scan counter for the next replay ----
    for (int i = blockIdx.x * MLP_THREADS + tid; i < N_NODES; i += MLP_GRID * MLP_THREADS)
        g_off[i] = 0;
    if (blockIdx.x == 0 && tid == 0) g_scan_ctr = 0;
}

extern "C" void kernel_launch(void* const* d_in, const int* in_sizes, int n_in,
                              void* d_out, int out_size)
{
    const float* y   = (const float*)d_in[0];
    const int*   sn  = (const int*)  d_in[1];
    const int*   en  = (const int*)  d_in[2];
    const float* dfs = (const float*)d_in[3];
    const float* df  = (const float*)d_in[4];
    const float* W1  = (const float*)d_in[5];
    const float* b1  = (const float*)d_in[6];
    const float* W2  = (const float*)d_in[7];
    const float* b2  = (const float*)d_in[8];
    float* out = (float*)d_out;

    float *bufA, *bufB;
    cudaGetSymbolAddress((void**)&bufA, g_bufA);
    cudaGetSymbolAddress((void**)&bufB, g_bufB);

    cudaFuncSetAttribute(mlp_kernel, cudaFuncAttributeMaxDynamicSharedMemorySize,
                         MLP_SMEM_WORDS * (int)sizeof(uint32_t));

    const bool tail = (out_size >= FULL_OUT);

    // ---- CSR build: hist -> fused scan -> fill ----
    hist_and_split<<<HB + WB, 256>>>(en, W1, W2);
    if (tail) {
        scan_fused<true><<<SCAN_BLOCKS, 256>>>(df, out);
        fill_kernel<true><<<EB, 256>>>(sn, en, dfs, out);
    } else {
        scan_fused<false><<<SCAN_BLOCKS, 256>>>(df, out);
        fill_kernel<false><<<EB, 256>>>(sn, en, dfs, out);
    }

    // ---- two gather passes ----
    gather_pass<<<GB, 256>>>(y,    bufA, df);
    gather_pass<<<GB, 256>>>(bufA, bufB, df);

    // ---- persistent fused tensor-core MLP (2xTF32), resets state at tail ----
    mlp_kernel<<<MLP_GRID, MLP_THREADS,
                 MLP_SMEM_WORDS * sizeof(uint32_t)>>>(bufB, b1, b2, out);
}